// round 4
// baseline (speedup 1.0000x reference)
#include <cuda_runtime.h>
#include <math.h>

#define NB 8
#define P  2048
#define EPSV 0.1f
#define KSCALE 14.426950408889634f   /* log2(e)/eps */
#define K2     28.853900817779268f   /* 2*KSCALE */

// ---------------- device scratch (no allocations allowed) ----------------
// Fused per-point operand: {coord0, coord1, b = (pot - s)*KSCALE, unused}
__device__ float4 g_xb[NB*P];
__device__ float4 g_yb[NB*P];
__device__ float  g_sx[NB*P];
__device__ float  g_sy[NB*P];
__device__ float  g_logmu[NB*P];
__device__ float  g_lognu[NB*P];
__device__ float  g_u[NB*P];
__device__ float  g_v[NB*P];
__device__ float  g_part[NB*P];

__device__ __forceinline__ float ex2f(float x){
    float y; asm("ex2.approx.ftz.f32 %0, %1;" : "=f"(y) : "f"(x)); return y;
}

// ---------------- init: mask, marginals, norms, operands, potentials=0 ---
__global__ void __launch_bounds__(512) init_k(const float* __restrict__ x,
                                              const float* __restrict__ y)
{
    int n = blockIdx.x, tid = threadIdx.x;
    __shared__ float sS[512], sT[512];
    float locS = 0.f, locT = 0.f;
    for (int i = tid; i < P; i += 512) {
        int idx = (n*P + i)*2;
        float x0 = x[idx], x1 = x[idx+1];
        float y0 = y[idx], y1 = y[idx+1];
        float m0 = (x0 != -1.0f) ? 1.0f : 0.0f;
        float m1 = (x1 != -1.0f) ? 1.0f : 0.0f;
        float xm0 = x0*m0, xm1 = x1*m1;
        float ym0 = y0*m0, ym1 = y1*m1;
        float sx = xm0*xm0 + xm1*xm1;
        float sy = ym0*ym0 + ym1*ym1;
        g_sx[n*P+i] = sx;
        g_sy[n*P+i] = sy;
        // pot = 0 initially -> b = -s*KSCALE
        g_xb[n*P+i] = make_float4(xm0, xm1, -sx*KSCALE, 0.f);
        g_yb[n*P+i] = make_float4(ym0, ym1, -sy*KSCALE, 0.f);
        locS += xm1*xm1;
        locT += ym1*ym1;
    }
    sS[tid] = locS; sT[tid] = locT;
    __syncthreads();
    for (int s = 256; s > 0; s >>= 1) {
        if (tid < s) { sS[tid] += sS[tid+s]; sT[tid] += sT[tid+s]; }
        __syncthreads();
    }
    float S = sS[0], T = sT[0];
    for (int i = tid; i < P; i += 512) {
        float xm1 = g_xb[n*P+i].y, ym1 = g_yb[n*P+i].y;
        g_logmu[n*P+i] = logf(xm1*xm1/S + 1e-8f);
        g_lognu[n*P+i] = logf(ym1*ym1/T + 1e-8f);
        g_u[n*P+i] = 0.f;
        g_v[n*P+i] = 0.f;
    }
}

// ---------------- one Sinkhorn half-step (u- or v-update) ----------------
// Identity: pot_new_i = s_self_i + EPS*(logmu_i - ln Σ_j exp2(b_j + dot_ij)),
//   with b_j = (pot_peer_j - s_peer_j)*KSCALE stored fused with the peer
//   coords (float4), dot_ij = 2*KSCALE*(x_i·y_j).
// No smem staging: peer operands read directly via LDG.128; the per-batch
// 32KB working set stays L1-resident (L1 flushed per launch -> coherent).
// Block 256 = 8 warps; warp (g,jh): 4 rows, half the j range.
// grid: (P/16, NB) = 1024 blocks.
__global__ void __launch_bounds__(256, 8) phase_k(int dir)
{
    __shared__ float sred[2][16];

    const float4* self = dir ? g_yb    : g_xb;
    float4*       peerW= dir ? g_yb    : g_xb;   // epilogue writes own .z
    const float4* peer = dir ? g_xb    : g_yb;
    const float*  s_self = dir ? g_sy  : g_sx;
    const float*  logm   = dir ? g_lognu : g_logmu;
    float*        pot    = dir ? g_v   : g_u;

    int n = blockIdx.y, bp = n*P;
    int tid = threadIdx.x, w = tid >> 5, lane = tid & 31;
    int g  = w & 3;       // row group within block (4 rows)
    int jh = w >> 2;      // which half of j
    int r0 = blockIdx.x*16 + g*4;

    float c0[4], c1[4], sum[4];
#pragma unroll
    for (int k = 0; k < 4; k++) {
        float4 xx = self[bp + r0 + k];
        c0[k] = K2 * xx.x;
        c1[k] = K2 * xx.y;
        sum[k] = 0.f;
    }

    const float4* pj = peer + bp;
    int jend = jh*1024 + 1024;
#pragma unroll 4
    for (int j = jh*1024 + lane; j < jend; j += 32) {
        float4 yv = pj[j];                 // {y0, y1, b, -}
#pragma unroll
        for (int k = 0; k < 4; k++) {
            float t = fmaf(c0[k], yv.x, fmaf(c1[k], yv.y, yv.z));
            sum[k] += ex2f(t);
        }
    }

#pragma unroll
    for (int k = 0; k < 4; k++) {
        float s = sum[k];
#pragma unroll
        for (int off = 16; off; off >>= 1) s += __shfl_xor_sync(0xffffffffu, s, off);
        if (lane == 0) sred[jh][g*4 + k] = s;
    }
    __syncthreads();

    if (tid < 16) {
        float s = sred[0][tid] + sred[1][tid];
        int i = bp + blockIdx.x*16 + tid;
        float pnew = s_self[i] + EPSV*(logm[i] - logf(fmaxf(s, 1e-35f)));
        pot[i] = pnew;
        peerW[i].z = (pnew - s_self[i]) * KSCALE;  // fused b for next phase
    }
}

// ---------------- finalize: write pi, C, per-row cost partials ----------
__global__ void __launch_bounds__(256) final_k(float* __restrict__ out)
{
    int n = blockIdx.y, i = blockIdx.x, tid = threadIdx.x;
    int bp = n*P;
    float4 xx = g_xb[bp + i];
    float u = g_u[bp + i];
    size_t base = ((size_t)bp + i) * P;
    float* out_pi = out + 8;
    float* out_C  = out + 8 + (size_t)NB*P*P;
    float acc = 0.f;
    for (int j = tid; j < P; j += 256) {
        float4 yy = g_yb[bp + j];
        float dx = xx.x - yy.x, dy = xx.y - yy.y;
        float C  = dx*dx + dy*dy;
        float pi = ex2f((u + g_v[bp+j] - C) * KSCALE);
        out_pi[base + j] = pi;
        out_C[base + j]  = C;
        acc = fmaf(pi, C, acc);
    }
    __shared__ float sred[256];
    sred[tid] = acc;
    __syncthreads();
    for (int s = 128; s > 0; s >>= 1) {
        if (tid < s) sred[tid] += sred[tid + s];
        __syncthreads();
    }
    if (tid == 0) g_part[bp + i] = sred[0];
}

// deterministic per-batch cost reduction (no float atomics)
__global__ void __launch_bounds__(256) cost_k(float* __restrict__ out)
{
    int n = blockIdx.x, tid = threadIdx.x;
    float acc = 0.f;
    for (int i = tid; i < P; i += 256) acc += g_part[n*P + i];
    __shared__ float sred[256];
    sred[tid] = acc;
    __syncthreads();
    for (int s = 128; s > 0; s >>= 1) {
        if (tid < s) sred[tid] += sred[tid + s];
        __syncthreads();
    }
    if (tid == 0) out[n] = sred[0];
}

// ---------------- launch ------------------------------------------------
extern "C" void kernel_launch(void* const* d_in, const int* in_sizes, int n_in,
                              void* d_out, int out_size)
{
    const float* x = (const float*)d_in[0];
    const float* y = (const float*)d_in[1];
    float* out = (float*)d_out;

    init_k<<<NB, 512>>>(x, y);
    for (int it = 0; it < 50; it++) {
        phase_k<<<dim3(P/16, NB), 256>>>(0);  // u-update
        phase_k<<<dim3(P/16, NB), 256>>>(1);  // v-update
    }
    final_k<<<dim3(P, NB), 256>>>(out);
    cost_k<<<NB, 256>>>(out);
}

// round 5
// speedup vs baseline: 1.3002x; 1.3002x over previous
#include <cuda_runtime.h>
#include <math.h>

#define NB 8
#define P  2048
#define EPSV 0.1f
#define KSCALE 14.426950408889634f   /* log2(e)/eps */
#define K2     28.853900817779268f   /* 2*KSCALE */
#define CHUNK  256
#define NCH    (P/CHUNK)             /* 8 */

// ---------------- device scratch (no allocations allowed) ----------------
// Fused per-point operand: {coord0, coord1, z = (pot - s)*KSCALE, pad}
__device__ float4 g_xf[NB*P];
__device__ float4 g_yf[NB*P];
__device__ float  g_l2mu[NB*P];
__device__ float  g_l2nu[NB*P];
__device__ float  g_part[NB*P];

__device__ __forceinline__ float ex2f(float x){
    float y; asm("ex2.approx.ftz.f32 %0, %1;" : "=f"(y) : "f"(x)); return y;
}
__device__ __forceinline__ float lg2f(float x){
    float y; asm("lg2.approx.ftz.f32 %0, %1;" : "=f"(y) : "f"(x)); return y;
}

// ---------------- init: mask, marginals, fused operands ------------------
__global__ void __launch_bounds__(512) init_k(const float* __restrict__ x,
                                              const float* __restrict__ y)
{
    int n = blockIdx.x, tid = threadIdx.x;
    __shared__ float sS[512], sT[512];
    float locS = 0.f, locT = 0.f;
    for (int i = tid; i < P; i += 512) {
        int idx = (n*P + i)*2;
        float x0 = x[idx], x1 = x[idx+1];
        float y0 = y[idx], y1 = y[idx+1];
        float m0 = (x0 != -1.0f) ? 1.0f : 0.0f;
        float m1 = (x1 != -1.0f) ? 1.0f : 0.0f;
        float xm0 = x0*m0, xm1 = x1*m1;
        float ym0 = y0*m0, ym1 = y1*m1;
        float sx = xm0*xm0 + xm1*xm1;
        float sy = ym0*ym0 + ym1*ym1;
        // pot = 0 initially -> z = -s*KSCALE
        g_xf[n*P+i] = make_float4(xm0, xm1, -sx*KSCALE, 0.f);
        g_yf[n*P+i] = make_float4(ym0, ym1, -sy*KSCALE, 0.f);
        locS += xm1*xm1;
        locT += ym1*ym1;
    }
    sS[tid] = locS; sT[tid] = locT;
    __syncthreads();
    for (int s = 256; s > 0; s >>= 1) {
        if (tid < s) { sS[tid] += sS[tid+s]; sT[tid] += sT[tid+s]; }
        __syncthreads();
    }
    float S = sS[0], T = sT[0];
    for (int i = tid; i < P; i += 512) {
        float xm1 = g_xf[n*P+i].y, ym1 = g_yf[n*P+i].y;
        // log2(mu + 1e-8) == ln(mu + 1e-8) * log2(e)
        g_l2mu[n*P+i] = log2f(xm1*xm1/S + 1e-8f);
        g_l2nu[n*P+i] = log2f(ym1*ym1/T + 1e-8f);
    }
}

// ---------------- one Sinkhorn half-step ----------------------------------
// z_i <- log2(mu_i) - log2( sum_j exp2( z_j + K2*(x_i . y_j) ) )
// where z = (pot - s)*KSCALE is stored fused with the coords (float4).
// Block 128 thr = 4 warps x 4 rows = 16 rows. grid (P/16, NB) = 1024 blocks.
// Peer operands streamed L2 -> smem in 8 double-buffered chunks of 256,
// staging overlapped with compute (XU/MUFU is the binding pipe).
__global__ void __launch_bounds__(128, 8) phase_k(int dir)
{
    __shared__ float4 buf[2][CHUNK];

    float4*       self = dir ? g_yf : g_xf;   // rows updated (.z); coords read
    const float4* peer = dir ? g_xf : g_yf;   // streamed side
    const float*  l2m  = dir ? g_l2nu : g_l2mu;

    int n = blockIdx.y, bp = n*P;
    int tid = threadIdx.x, w = tid >> 5, lane = tid & 31;
    int r0 = blockIdx.x*16 + w*4;

    const float4* pj = peer + bp;

    // stage chunk 0 (front-batched before self-row loads finish)
    buf[0][tid]       = pj[tid];
    buf[0][tid + 128] = pj[tid + 128];

    float c0[4], c1[4], sum[4];
#pragma unroll
    for (int k = 0; k < 4; k++) {
        float4 xx = self[bp + r0 + k];
        c0[k] = K2 * xx.x;
        c1[k] = K2 * xx.y;
        sum[k] = 0.f;
    }
    __syncthreads();

#pragma unroll 1
    for (int c = 0; c < NCH; c++) {
        int cb = c & 1, nb = cb ^ 1;
        float4 p0, p1;
        if (c < NCH-1) {                       // prefetch next chunk
            p0 = pj[(c+1)*CHUNK + tid];
            p1 = pj[(c+1)*CHUNK + tid + 128];
        }
#pragma unroll
        for (int jj = 0; jj < CHUNK/32; jj++) {
            float4 yv = buf[cb][jj*32 + lane];
#pragma unroll
            for (int k = 0; k < 4; k++) {
                float t = fmaf(c0[k], yv.x, fmaf(c1[k], yv.y, yv.z));
                sum[k] += ex2f(t);
            }
        }
        if (c < NCH-1) {
            buf[nb][tid]       = p0;
            buf[nb][tid + 128] = p1;
        }
        __syncthreads();
    }

#pragma unroll
    for (int k = 0; k < 4; k++) {
#pragma unroll
        for (int off = 16; off; off >>= 1)
            sum[k] += __shfl_xor_sync(0xffffffffu, sum[k], off);
    }
    if (lane == 0) {
#pragma unroll
        for (int k = 0; k < 4; k++) {
            int i = bp + r0 + k;
            float z = l2m[i] - lg2f(fmaxf(sum[k], 1e-35f));
            ((float*)&self[i])[2] = z;         // STG.32 of the .z field
        }
    }
}

// ---------------- finalize: write pi, C, per-row cost partials -----------
// pi_ij = exp2( xz_i + yz_j + K2*(x_i . y_j) ),  C recomputed from coords.
__global__ void __launch_bounds__(256) final_k(float* __restrict__ out)
{
    int n = blockIdx.y, i = blockIdx.x, tid = threadIdx.x;
    int bp = n*P;
    float4 xx = g_xf[bp + i];
    float a0 = K2*xx.x, a1 = K2*xx.y, az = xx.z;
    size_t base = ((size_t)bp + i) * P;
    float* out_pi = out + 8;
    float* out_C  = out + 8 + (size_t)NB*P*P;
    float acc = 0.f;
    for (int j = tid; j < P; j += 256) {
        float4 yy = g_yf[bp + j];
        float dx = xx.x - yy.x, dy = xx.y - yy.y;
        float C  = dx*dx + dy*dy;
        float pi = ex2f(fmaf(a0, yy.x, fmaf(a1, yy.y, az + yy.z)));
        out_pi[base + j] = pi;
        out_C[base + j]  = C;
        acc = fmaf(pi, C, acc);
    }
    __shared__ float sred[256];
    sred[tid] = acc;
    __syncthreads();
    for (int s = 128; s > 0; s >>= 1) {
        if (tid < s) sred[tid] += sred[tid + s];
        __syncthreads();
    }
    if (tid == 0) g_part[bp + i] = sred[0];
}

// deterministic per-batch cost reduction (no float atomics)
__global__ void __launch_bounds__(256) cost_k(float* __restrict__ out)
{
    int n = blockIdx.x, tid = threadIdx.x;
    float acc = 0.f;
    for (int i = tid; i < P; i += 256) acc += g_part[n*P + i];
    __shared__ float sred[256];
    sred[tid] = acc;
    __syncthreads();
    for (int s = 128; s > 0; s >>= 1) {
        if (tid < s) sred[tid] += sred[tid + s];
        __syncthreads();
    }
    if (tid == 0) out[n] = sred[0];
}

// ---------------- launch ------------------------------------------------
extern "C" void kernel_launch(void* const* d_in, const int* in_sizes, int n_in,
                              void* d_out, int out_size)
{
    const float* x = (const float*)d_in[0];
    const float* y = (const float*)d_in[1];
    float* out = (float*)d_out;

    init_k<<<NB, 512>>>(x, y);
    for (int it = 0; it < 50; it++) {
        phase_k<<<dim3(P/16, NB), 128>>>(0);  // u-update (x side)
        phase_k<<<dim3(P/16, NB), 128>>>(1);  // v-update (y side)
    }
    final_k<<<dim3(P, NB), 256>>>(out);
    cost_k<<<NB, 256>>>(out);
}

// round 6
// speedup vs baseline: 1.3153x; 1.0117x over previous
#include <cuda_runtime.h>
#include <math.h>

#define NB 8
#define P  2048
#define KSCALE 14.426950408889634f   /* log2(e)/eps */
#define K2     28.853900817779268f   /* 2*KSCALE */
#define CHUNK  256
#define NCH    (P/CHUNK)             /* 8 */
#define BLKS_PER_BATCH 128
#define NITER  50

// ---------------- device scratch (no allocations allowed) ----------------
// Fused per-point operand: {coord0, coord1, z = (pot - s)*KSCALE, pad}
__device__ float4   g_xf[NB*P];
__device__ float4   g_yf[NB*P];
__device__ float    g_l2mu[NB*P];
__device__ float    g_l2nu[NB*P];
__device__ float    g_part[NB*P];
__device__ unsigned g_cnt[NB*32];    // one 128B line per batch
__device__ unsigned g_gen[NB*32];

__device__ __forceinline__ float ex2f(float x){
    float y; asm("ex2.approx.ftz.f32 %0, %1;" : "=f"(y) : "f"(x)); return y;
}
__device__ __forceinline__ float lg2f(float x){
    float y; asm("lg2.approx.ftz.f32 %0, %1;" : "=f"(y) : "f"(x)); return y;
}

// ---------------- init: mask, marginals, fused operands ------------------
__global__ void __launch_bounds__(512) init_k(const float* __restrict__ x,
                                              const float* __restrict__ y)
{
    int n = blockIdx.x, tid = threadIdx.x;
    __shared__ float sS[512], sT[512];
    float locS = 0.f, locT = 0.f;
    for (int i = tid; i < P; i += 512) {
        int idx = (n*P + i)*2;
        float x0 = x[idx], x1 = x[idx+1];
        float y0 = y[idx], y1 = y[idx+1];
        float m0 = (x0 != -1.0f) ? 1.0f : 0.0f;
        float m1 = (x1 != -1.0f) ? 1.0f : 0.0f;
        float xm0 = x0*m0, xm1 = x1*m1;
        float ym0 = y0*m0, ym1 = y1*m1;
        float sx = xm0*xm0 + xm1*xm1;
        float sy = ym0*ym0 + ym1*ym1;
        // pot = 0 initially -> z = -s*KSCALE
        g_xf[n*P+i] = make_float4(xm0, xm1, -sx*KSCALE, 0.f);
        g_yf[n*P+i] = make_float4(ym0, ym1, -sy*KSCALE, 0.f);
        locS += xm1*xm1;
        locT += ym1*ym1;
    }
    sS[tid] = locS; sT[tid] = locT;
    __syncthreads();
    for (int s = 256; s > 0; s >>= 1) {
        if (tid < s) { sS[tid] += sS[tid+s]; sT[tid] += sT[tid+s]; }
        __syncthreads();
    }
    float S = sS[0], T = sT[0];
    for (int i = tid; i < P; i += 512) {
        float xm1 = g_xf[n*P+i].y, ym1 = g_yf[n*P+i].y;
        g_l2mu[n*P+i] = log2f(xm1*xm1/S + 1e-8f);
        g_l2nu[n*P+i] = log2f(ym1*ym1/T + 1e-8f);
    }
}

// ---------------- per-batch barrier (sense-reversing, 128 arrivals) ------
__device__ __forceinline__ void batch_barrier(unsigned* cnt, volatile unsigned* gen,
                                              int tid)
{
    __syncthreads();                 // all warps in block done storing z
    if (tid == 0) {
        __threadfence();             // release: z stores -> L2 before arrive
        unsigned g = *gen;
        if (atomicAdd(cnt, 1u) == BLKS_PER_BATCH - 1u) {
            atomicExch(cnt, 0u);
            __threadfence();
            atomicAdd((unsigned*)gen, 1u);
        } else {
            while (*gen == g) __nanosleep(64);
        }
    }
    __syncthreads();
    __threadfence();                 // acquire side for all threads
}

// ---------------- one Sinkhorn half-step (inlined into persist_k) --------
// z_i <- log2(mu_i) - log2( sum_j exp2( z_j + K2*(x_i . y_j) ) )
// Peer streamed L2->smem (ldcg: L1 is stale across phases within the kernel),
// 8 double-buffered chunks of 256; MUFU is the binding pipe.
__device__ __forceinline__ void half_step(
    const float (&c0)[4], const float (&c1)[4], const float (&l2)[4],
    const float4* __restrict__ pj, float4* selfp,
    int r0, int tid, int w, int lane, float4 (*buf)[CHUNK])
{
    buf[0][tid]       = __ldcg(pj + tid);
    buf[0][tid + 128] = __ldcg(pj + tid + 128);
    float sum[4] = {0.f, 0.f, 0.f, 0.f};
    __syncthreads();

#pragma unroll 1
    for (int c = 0; c < NCH; c++) {
        int cb = c & 1;
        float4 p0, p1;
        if (c < NCH-1) {                       // prefetch next chunk
            p0 = __ldcg(pj + (c+1)*CHUNK + tid);
            p1 = __ldcg(pj + (c+1)*CHUNK + tid + 128);
        }
#pragma unroll
        for (int jj = 0; jj < CHUNK/32; jj++) {
            float4 yv = buf[cb][jj*32 + lane];
#pragma unroll
            for (int k = 0; k < 4; k++) {
                float t = fmaf(c0[k], yv.x, fmaf(c1[k], yv.y, yv.z));
                sum[k] += ex2f(t);
            }
        }
        if (c < NCH-1) {
            buf[cb^1][tid]       = p0;
            buf[cb^1][tid + 128] = p1;
        }
        __syncthreads();
    }

#pragma unroll
    for (int k = 0; k < 4; k++) {
#pragma unroll
        for (int off = 16; off; off >>= 1)
            sum[k] += __shfl_xor_sync(0xffffffffu, sum[k], off);
    }
    if (lane == 0) {
#pragma unroll
        for (int k = 0; k < 4; k++) {
            float z = l2[k] - lg2f(fmaxf(sum[k], 1e-35f));
            __stcg(((float*)&selfp[r0 + k]) + 2, z);
        }
    }
}

// ---------------- persistent kernel: all 100 half-steps ------------------
// 1024 blocks x 128 thr; 8 blocks/SM guaranteed resident (regs<=64, 8KB smem,
// 32 warps/SM). Batches sync independently (128-block barriers).
__global__ void __launch_bounds__(128, 8) persist_k()
{
    __shared__ float4 buf[2][CHUNK];

    int b = blockIdx.x;
    int n = b >> 7;                  // batch
    int rb = b & 127;                // row block within batch
    int bp = n*P;
    int tid = threadIdx.x, w = tid >> 5, lane = tid & 31;
    int r0 = rb*16 + w*4;

    float4* xf = g_xf + bp;
    float4* yf = g_yf + bp;

    // iteration-invariant row data for BOTH sides, loaded once
    float c0x[4], c1x[4], c0y[4], c1y[4], l2x[4], l2y[4];
#pragma unroll
    for (int k = 0; k < 4; k++) {
        float4 xx = xf[r0 + k];
        float4 yy = yf[r0 + k];
        c0x[k] = K2*xx.x; c1x[k] = K2*xx.y;
        c0y[k] = K2*yy.x; c1y[k] = K2*yy.y;
        l2x[k] = g_l2mu[bp + r0 + k];
        l2y[k] = g_l2nu[bp + r0 + k];
    }

    unsigned*          cnt = &g_cnt[n*32];
    volatile unsigned* gen = &g_gen[n*32];

#pragma unroll 1
    for (int it = 0; it < NITER; it++) {
        half_step(c0x, c1x, l2x, yf, xf, r0, tid, w, lane, buf);  // u-update
        batch_barrier(cnt, gen, tid);
        half_step(c0y, c1y, l2y, xf, yf, r0, tid, w, lane, buf);  // v-update
        batch_barrier(cnt, gen, tid);
    }
}

// ---------------- finalize: write pi, C, per-row cost partials -----------
__global__ void __launch_bounds__(256) final_k(float* __restrict__ out)
{
    int n = blockIdx.y, i = blockIdx.x, tid = threadIdx.x;
    int bp = n*P;
    float4 xx = g_xf[bp + i];
    float a0 = K2*xx.x, a1 = K2*xx.y, az = xx.z;
    size_t base = ((size_t)bp + i) * P;
    float* out_pi = out + 8;
    float* out_C  = out + 8 + (size_t)NB*P*P;
    float acc = 0.f;
    for (int j = tid; j < P; j += 256) {
        float4 yy = g_yf[bp + j];
        float dx = xx.x - yy.x, dy = xx.y - yy.y;
        float C  = dx*dx + dy*dy;
        float pi = ex2f(fmaf(a0, yy.x, fmaf(a1, yy.y, az + yy.z)));
        out_pi[base + j] = pi;
        out_C[base + j]  = C;
        acc = fmaf(pi, C, acc);
    }
    __shared__ float sred[256];
    sred[tid] = acc;
    __syncthreads();
    for (int s = 128; s > 0; s >>= 1) {
        if (tid < s) sred[tid] += sred[tid + s];
        __syncthreads();
    }
    if (tid == 0) g_part[bp + i] = sred[0];
}

// deterministic per-batch cost reduction (no float atomics)
__global__ void __launch_bounds__(256) cost_k(float* __restrict__ out)
{
    int n = blockIdx.x, tid = threadIdx.x;
    float acc = 0.f;
    for (int i = tid; i < P; i += 256) acc += g_part[n*P + i];
    __shared__ float sred[256];
    sred[tid] = acc;
    __syncthreads();
    for (int s = 128; s > 0; s >>= 1) {
        if (tid < s) sred[tid] += sred[tid + s];
        __syncthreads();
    }
    if (tid == 0) out[n] = sred[0];
}

// ---------------- launch ------------------------------------------------
extern "C" void kernel_launch(void* const* d_in, const int* in_sizes, int n_in,
                              void* d_out, int out_size)
{
    const float* x = (const float*)d_in[0];
    const float* y = (const float*)d_in[1];
    float* out = (float*)d_out;

    init_k<<<NB, 512>>>(x, y);
    persist_k<<<NB*BLKS_PER_BATCH, 128>>>();
    final_k<<<dim3(P, NB), 256>>>(out);
    cost_k<<<NB, 256>>>(out);
}